// round 10
// baseline (speedup 1.0000x reference)
#include <cuda_runtime.h>
#include <cuda_bf16.h>

#define T_BINS 16384
#define EDGE   4
#define WIN    9      // 2*EDGE+1
#define D_DIM  128    // 32 float4 per row

// One warp per batch element. Lane l owns output floats [4l, 4l+4).
//
// Bin math is done analytically: edges are i * 2^-14 (exact fp32 since the
// linspace step is a power of two), so:
//   xi = x * 16384           (exact: power-of-two scale)
//   i  = floor(xi)           (containment bin)
//   tie (x exactly on an interior edge) <=> xi == (float)i, and the
//   reference's argmax picks the LOWER bin -> decrement.
//   d0 = (x - et[i]) / wide  ==  xi - (i + 0.5)   bit-exactly
// (scaling by 2^14 commutes with fp32 rounding; xi is a multiple of 2^-10,
// so all subsequent subtractions of small integers are exact).
// This removes every pre-gather table load: the 9 gather addresses depend
// only on the x load, collapsing the dependent chain to 2 memory latencies.
__global__ void __launch_bounds__(256, 4)
hwnet_kernel(const float* __restrict__ xin,
             const float* __restrict__ vt,
             float* __restrict__ out,
             int B)
{
    int warp = (int)((blockIdx.x * blockDim.x + threadIdx.x) >> 5);
    int lane = threadIdx.x & 31;
    if (warp >= B) return;

    float x  = __ldg(&xin[warp]);
    float xi = x * (float)T_BINS;            // exact
    int   i  = (int)xi;                      // floor, x >= 0
    i = min(i, T_BINS - 1);
    if (i > 0 && (float)i == xi) --i;        // argmax tie -> lower bin

    int ic = min(max(i, EDGE), T_BINS - 1 - EDGE);

    // Issue all 9 gathers immediately (addresses depend only on x).
    const float4* vt4 = (const float4*)vt;
    size_t row0 = (size_t)(ic - EDGE) * 32 + (size_t)lane;
    float4 v[WIN];
    #pragma unroll
    for (int w = 0; w < WIN; ++w)
        v[w] = __ldg(&vt4[row0 + (size_t)w * 32]);

    // Softmax weights (overlap with gathers in flight).
    // One exp per lane for lanes 0..8 (32x fewer MUFU ops). No max-subtract
    // needed: terms are exp(-10 d^2) <= 1 and the nearest bin guarantees the
    // max term >= exp(-2.5); far terms underflow harmlessly.
    float d0   = xi - ((float)i + 0.5f);     // bit-exact vs reference
    float base = d0 - (float)(ic - i);       // exact (<=14-bit values)

    float e = 0.0f;
    if (lane < WIN) {
        float d = base - (float)(lane - EDGE);
        e = __expf(-10.0f * d * d);
    }
    float s = e;
    #pragma unroll
    for (int off = 16; off > 0; off >>= 1)
        s += __shfl_xor_sync(0xffffffffu, s, off);
    float inv = 1.0f / s;

    float4 acc = make_float4(0.f, 0.f, 0.f, 0.f);
    #pragma unroll
    for (int w = 0; w < WIN; ++w) {
        float wt = __shfl_sync(0xffffffffu, e, w) * inv;
        acc.x = fmaf(v[w].x, wt, acc.x);
        acc.y = fmaf(v[w].y, wt, acc.y);
        acc.z = fmaf(v[w].z, wt, acc.z);
        acc.w = fmaf(v[w].w, wt, acc.w);
    }
    ((float4*)out)[(size_t)warp * 32 + lane] = acc;
}

extern "C" void kernel_launch(void* const* d_in, const int* in_sizes, int n_in,
                              void* d_out, int out_size)
{
    // metadata order: inputs [B,1], evaluate_table [T,1], evaluate_min_table [T,1],
    //                 evaluate_max_table [T,1], vector_table [T,D]
    const float* xin = (const float*)d_in[0];
    const float* vt  = (const float*)d_in[4];
    float* out = (float*)d_out;

    int B = in_sizes[0];                 // 8192
    int threads = 256;                   // 8 warps/block, 1 sample per warp
    int blocks  = (B * 32 + threads - 1) / threads;

    hwnet_kernel<<<blocks, threads>>>(xin, vt, out, B);
}

// round 11
// speedup vs baseline: 1.0257x; 1.0257x over previous
#include <cuda_runtime.h>
#include <cuda_bf16.h>

#define T_BINS 16384
#define EDGE   4
#define WIN    9      // 2*EDGE+1
#define D_DIM  128    // 32 float4 per row

// One warp per batch element. Lane l owns output floats [4l, 4l+4).
//
// Analytic bin math (no table loads): edges are i * 2^-14, exact in fp32,
// so xi = x*16384 is exact, i = floor(xi) is the containment bin, the
// argmax tie (x exactly on an interior edge) is xi == (float)i -> lower bin,
// and d0 = (x - et[i]) / wide == xi - (i + 0.5) bit-exactly.
//
// Register discipline: __launch_bounds__(256, 8) caps regs at 32 so all
// 8192 warps fit in ONE wave (55.4 warps/SM). Gathers are split 5 + 4 so
// peak live float4s = 5 (20 regs), avoiding spills, and front-batched
// MLP stays at 5 to limit cross-CTA L1tex-queue spread.
__global__ void __launch_bounds__(256, 8)
hwnet_kernel(const float* __restrict__ xin,
             const float* __restrict__ vt,
             float* __restrict__ out,
             int B)
{
    int warp = (int)((blockIdx.x * blockDim.x + threadIdx.x) >> 5);
    int lane = threadIdx.x & 31;
    if (warp >= B) return;

    float x  = __ldg(&xin[warp]);
    float xi = x * (float)T_BINS;            // exact (power-of-two scale)
    int   i  = (int)xi;                      // floor, x >= 0
    i = min(i, T_BINS - 1);
    if (i > 0 && (float)i == xi) --i;        // argmax tie -> lower bin

    int ic = min(max(i, EDGE), T_BINS - 1 - EDGE);

    const float4* vt4 = (const float4*)vt;
    size_t row0 = (size_t)(ic - EDGE) * 32 + (size_t)lane;

    // Batch 1: 5 gathers in flight while weights are computed.
    float4 v0 = __ldg(&vt4[row0]);
    float4 v1 = __ldg(&vt4[row0 + 32]);
    float4 v2 = __ldg(&vt4[row0 + 64]);
    float4 v3 = __ldg(&vt4[row0 + 96]);
    float4 v4 = __ldg(&vt4[row0 + 128]);

    // Softmax weights: one exp per lane for lanes 0..8 (32x fewer MUFU ops),
    // warp-reduced sum, weights broadcast via shfl. No max-subtraction
    // needed: terms are exp(-10 d^2) <= 1 and the nearest bin guarantees
    // max term >= exp(-2.5); far terms underflow harmlessly.
    float d0   = xi - ((float)i + 0.5f);     // bit-exact vs reference
    float base = d0 - (float)(ic - i);       // exact (small-integer offsets)

    float e = 0.0f;
    if (lane < WIN) {
        float d = base - (float)(lane - EDGE);
        e = __expf(-10.0f * d * d);
    }
    float s = e;
    #pragma unroll
    for (int off = 16; off > 0; off >>= 1)
        s += __shfl_xor_sync(0xffffffffu, s, off);
    float inv = 1.0f / s;

    float w0 = __shfl_sync(0xffffffffu, e, 0) * inv;
    float w1 = __shfl_sync(0xffffffffu, e, 1) * inv;
    float w2 = __shfl_sync(0xffffffffu, e, 2) * inv;
    float w3 = __shfl_sync(0xffffffffu, e, 3) * inv;
    float w4 = __shfl_sync(0xffffffffu, e, 4) * inv;

    float4 acc;
    acc.x = v0.x * w0; acc.y = v0.y * w0; acc.z = v0.z * w0; acc.w = v0.w * w0;
    acc.x = fmaf(v1.x, w1, acc.x); acc.y = fmaf(v1.y, w1, acc.y);
    acc.z = fmaf(v1.z, w1, acc.z); acc.w = fmaf(v1.w, w1, acc.w);
    acc.x = fmaf(v2.x, w2, acc.x); acc.y = fmaf(v2.y, w2, acc.y);
    acc.z = fmaf(v2.z, w2, acc.z); acc.w = fmaf(v2.w, w2, acc.w);
    acc.x = fmaf(v3.x, w3, acc.x); acc.y = fmaf(v3.y, w3, acc.y);
    acc.z = fmaf(v3.z, w3, acc.z); acc.w = fmaf(v3.w, w3, acc.w);
    acc.x = fmaf(v4.x, w4, acc.x); acc.y = fmaf(v4.y, w4, acc.y);
    acc.z = fmaf(v4.z, w4, acc.z); acc.w = fmaf(v4.w, w4, acc.w);

    // Batch 2: remaining 4 gathers (regs from batch 1 now free).
    float4 v5 = __ldg(&vt4[row0 + 160]);
    float4 v6 = __ldg(&vt4[row0 + 192]);
    float4 v7 = __ldg(&vt4[row0 + 224]);
    float4 v8 = __ldg(&vt4[row0 + 256]);

    float w5 = __shfl_sync(0xffffffffu, e, 5) * inv;
    float w6 = __shfl_sync(0xffffffffu, e, 6) * inv;
    float w7 = __shfl_sync(0xffffffffu, e, 7) * inv;
    float w8 = __shfl_sync(0xffffffffu, e, 8) * inv;

    acc.x = fmaf(v5.x, w5, acc.x); acc.y = fmaf(v5.y, w5, acc.y);
    acc.z = fmaf(v5.z, w5, acc.z); acc.w = fmaf(v5.w, w5, acc.w);
    acc.x = fmaf(v6.x, w6, acc.x); acc.y = fmaf(v6.y, w6, acc.y);
    acc.z = fmaf(v6.z, w6, acc.z); acc.w = fmaf(v6.w, w6, acc.w);
    acc.x = fmaf(v7.x, w7, acc.x); acc.y = fmaf(v7.y, w7, acc.y);
    acc.z = fmaf(v7.z, w7, acc.z); acc.w = fmaf(v7.w, w7, acc.w);
    acc.x = fmaf(v8.x, w8, acc.x); acc.y = fmaf(v8.y, w8, acc.y);
    acc.z = fmaf(v8.z, w8, acc.z); acc.w = fmaf(v8.w, w8, acc.w);

    ((float4*)out)[(size_t)warp * 32 + lane] = acc;
}

extern "C" void kernel_launch(void* const* d_in, const int* in_sizes, int n_in,
                              void* d_out, int out_size)
{
    // metadata order: inputs [B,1], evaluate_table [T,1], evaluate_min_table [T,1],
    //                 evaluate_max_table [T,1], vector_table [T,D]
    const float* xin = (const float*)d_in[0];
    const float* vt  = (const float*)d_in[4];
    float* out = (float*)d_out;

    int B = in_sizes[0];                 // 8192
    int threads = 256;                   // 8 warps/block, 1 sample per warp
    int blocks  = (B * 32 + threads - 1) / threads;

    hwnet_kernel<<<blocks, threads>>>(xin, vt, out, B);
}

// round 12
// speedup vs baseline: 1.0528x; 1.0264x over previous
#include <cuda_runtime.h>
#include <cuda_bf16.h>

#define T_BINS 16384
#define EDGE   4
#define WIN    9      // 2*EDGE+1
#define D_DIM  128    // 32 float4 per row

#define WARPS_PER_BLK 8
#define SMEM_ROWS     6   // rows 3..8 go through cp.async -> smem

// One warp per batch element. Lane l owns output floats [4l, 4l+4).
//
// Analytic bin math (no table loads): edges are i * 2^-14, exact in fp32:
//   xi = x*16384 exact; i = floor(xi); argmax tie (x exactly on an interior
//   edge <=> xi == (float)i) resolves to the LOWER bin; and
//   d0 = (x - et[i]) / wide == xi - (i + 0.5) bit-exactly.
//
// Memory plan: all 9 row-fetches issue in ONE batch (single L2/DRAM round
// trip). Rows 0..2 are register LDG.128s (12 payload regs); rows 3..8 are
// cp.async.cg 16B copies into smem (zero payload regs). Each lane copies
// and later reads back ONLY its own 16B slot, so cp.async.wait_group 0
// gives sufficient visibility -- no barrier needed. Softmax weights
// (lanes 0..8 each compute one exp, warp-reduce, shfl-broadcast) overlap
// the fetch latency.
__global__ void __launch_bounds__(256, 7)
hwnet_kernel(const float* __restrict__ xin,
             const float* __restrict__ vt,
             float* __restrict__ out,
             int B)
{
    __shared__ __align__(16) uint4 sbuf[WARPS_PER_BLK][SMEM_ROWS][32];

    int warp = (int)((blockIdx.x * blockDim.x + threadIdx.x) >> 5);
    int wib  = (int)(threadIdx.x >> 5);
    int lane = (int)(threadIdx.x & 31);
    if (warp >= B) return;

    float x  = __ldg(&xin[warp]);
    float xi = x * (float)T_BINS;            // exact (power-of-two scale)
    int   i  = (int)xi;                      // floor, x >= 0
    i = min(i, T_BINS - 1);
    if (i > 0 && (float)i == xi) --i;        // argmax tie -> lower bin

    int ic = min(max(i, EDGE), T_BINS - 1 - EDGE);

    const float4* vt4 = (const float4*)vt;
    size_t row0 = (size_t)(ic - EDGE) * 32 + (size_t)lane;

    // ---- single fetch batch: 3 LDG + 6 cp.async ----
    float4 v0 = __ldg(&vt4[row0]);
    float4 v1 = __ldg(&vt4[row0 + 32]);
    float4 v2 = __ldg(&vt4[row0 + 64]);

    #pragma unroll
    for (int r = 0; r < SMEM_ROWS; ++r) {
        unsigned saddr = (unsigned)__cvta_generic_to_shared(&sbuf[wib][r][lane]);
        const float4* gptr = &vt4[row0 + (size_t)(r + 3) * 32];
        asm volatile("cp.async.cg.shared.global [%0], [%1], 16;"
                     :: "r"(saddr), "l"(gptr));
    }
    asm volatile("cp.async.commit_group;");

    // ---- softmax weights (overlap with fetches in flight) ----
    // One exp per lane for lanes 0..8 (32x fewer MUFU ops). No max-subtract
    // needed: terms are exp(-10 d^2) <= 1 and the nearest bin guarantees the
    // max term >= exp(-2.5); far terms underflow harmlessly.
    float d0   = xi - ((float)i + 0.5f);     // bit-exact vs reference
    float base = d0 - (float)(ic - i);       // exact (small-integer offsets)

    float e = 0.0f;
    if (lane < WIN) {
        float d = base - (float)(lane - EDGE);
        e = __expf(-10.0f * d * d);
    }
    float s = e;
    #pragma unroll
    for (int off = 16; off > 0; off >>= 1)
        s += __shfl_xor_sync(0xffffffffu, s, off);
    float inv = 1.0f / s;

    float w0 = __shfl_sync(0xffffffffu, e, 0) * inv;
    float w1 = __shfl_sync(0xffffffffu, e, 1) * inv;
    float w2 = __shfl_sync(0xffffffffu, e, 2) * inv;

    float4 acc;
    acc.x = v0.x * w0; acc.y = v0.y * w0; acc.z = v0.z * w0; acc.w = v0.w * w0;
    acc.x = fmaf(v1.x, w1, acc.x); acc.y = fmaf(v1.y, w1, acc.y);
    acc.z = fmaf(v1.z, w1, acc.z); acc.w = fmaf(v1.w, w1, acc.w);
    acc.x = fmaf(v2.x, w2, acc.x); acc.y = fmaf(v2.y, w2, acc.y);
    acc.z = fmaf(v2.z, w2, acc.z); acc.w = fmaf(v2.w, w2, acc.w);

    // ---- consume smem rows (arrived during the same round trip) ----
    asm volatile("cp.async.wait_group 0;");

    #pragma unroll
    for (int r = 0; r < SMEM_ROWS; ++r) {
        float wt = __shfl_sync(0xffffffffu, e, r + 3) * inv;
        float4 v = *(const float4*)&sbuf[wib][r][lane];
        acc.x = fmaf(v.x, wt, acc.x);
        acc.y = fmaf(v.y, wt, acc.y);
        acc.z = fmaf(v.z, wt, acc.z);
        acc.w = fmaf(v.w, wt, acc.w);
    }

    ((float4*)out)[(size_t)warp * 32 + lane] = acc;
}

extern "C" void kernel_launch(void* const* d_in, const int* in_sizes, int n_in,
                              void* d_out, int out_size)
{
    // metadata order: inputs [B,1], evaluate_table [T,1], evaluate_min_table [T,1],
    //                 evaluate_max_table [T,1], vector_table [T,D]
    const float* xin = (const float*)d_in[0];
    const float* vt  = (const float*)d_in[4];
    float* out = (float*)d_out;

    int B = in_sizes[0];                 // 8192
    int threads = 32 * WARPS_PER_BLK;    // 256: 8 warps/block, 1 sample/warp
    int blocks  = (B + WARPS_PER_BLK - 1) / WARPS_PER_BLK;

    hwnet_kernel<<<blocks, threads>>>(xin, vt, out, B);
}